// round 3
// baseline (speedup 1.0000x reference)
#include <cuda_runtime.h>
#include <mma.h>
using namespace nvcuda;

#define NH  32
#define NKV 8
#define HD  128
#define MAX_TOK 2048

// Scratch (no cudaMalloc allowed): q/att 33.5MB each, k/v 8.4MB each.
__device__ float g_q[MAX_TOK * NH * HD];
__device__ float g_k[MAX_TOK * NKV * HD];
__device__ float g_v[MAX_TOK * NKV * HD];
__device__ float g_att[MAX_TOK * NH * HD];

// ---------------- f32x2 packed-FMA helpers (sm_103a FFMA2 path) ----------------
__device__ __forceinline__ unsigned long long pk2(float lo, float hi) {
    unsigned long long r;
    asm("mov.b64 %0, {%1, %2};" : "=l"(r) : "f"(lo), "f"(hi));
    return r;
}
__device__ __forceinline__ void upk2(unsigned long long v, float& lo, float& hi) {
    asm("mov.b64 {%0, %1}, %2;" : "=f"(lo), "=f"(hi) : "l"(v));
}
__device__ __forceinline__ void ffma2(unsigned long long& d, unsigned long long a,
                                      unsigned long long b) {
    asm("fma.rn.f32x2 %0, %1, %2, %0;" : "+l"(d) : "l"(a), "l"(b));
}
__device__ __forceinline__ unsigned long long mul2(unsigned long long a,
                                                   unsigned long long b) {
    unsigned long long r;
    asm("mul.rn.f32x2 %0, %1, %2;" : "=l"(r) : "l"(a), "l"(b));
    return r;
}

union F8 {
    float f[8];
    float4 v[2];
    unsigned long long u[4];
};

// ---------------- tf32 tensor-core GEMM: C[M,N] = A[M,K] @ B[K,N] --------------
// 128x128 block tile, BK=16, 256 thr (8 warps in 4x2), warp tile 32x64,
// wmma m16n16k8 tf32 fragments, fp32 accumulate.
#define AS_STRIDE 20
#define BS_STRIDE 132

__device__ __forceinline__ void tf32_tile_body(
    const float* __restrict__ A, const float* __restrict__ B, float* __restrict__ C,
    int N, int K, int brow, int bcol, float* As, float* Bs)
{
    const int tid  = threadIdx.x;
    const int warp = tid >> 5;
    const int wr   = warp >> 1;   // 0..3 -> m offset 32*wr
    const int wc   = warp & 1;    // 0..1 -> n offset 64*wc

    wmma::fragment<wmma::accumulator, 16, 16, 8, float> acc[2][4];
    #pragma unroll
    for (int i = 0; i < 2; i++)
        #pragma unroll
        for (int j = 0; j < 4; j++)
            wmma::fill_fragment(acc[i][j], 0.0f);

    // A tile 128x16: 512 float4, 2 per thread. B tile 16x128: same.
    const int ar0 = tid >> 2,        ac0 = (tid & 3) * 4;
    const int ar1 = (tid >> 2) + 64;
    const int br0 = tid >> 5,        bc0 = (tid & 31) * 4;
    const int br1 = br0 + 8;

    const float* Ap = A + (size_t)brow * K;
    const float* Bp = B + bcol;

    float4 av0 = *(const float4*)(Ap + (size_t)ar0 * K + ac0);
    float4 av1 = *(const float4*)(Ap + (size_t)ar1 * K + ac0);
    float4 bv0 = *(const float4*)(Bp + (size_t)br0 * N + bc0);
    float4 bv1 = *(const float4*)(Bp + (size_t)br1 * N + bc0);

    for (int kt = 0; kt < K; kt += 16) {
        *(float4*)&As[ar0 * AS_STRIDE + ac0] = av0;
        *(float4*)&As[ar1 * AS_STRIDE + ac0] = av1;
        *(float4*)&Bs[br0 * BS_STRIDE + bc0] = bv0;
        *(float4*)&Bs[br1 * BS_STRIDE + bc0] = bv1;
        __syncthreads();
        if (kt + 16 < K) {   // prefetch next k-tile during compute
            av0 = *(const float4*)(Ap + (size_t)ar0 * K + kt + 16 + ac0);
            av1 = *(const float4*)(Ap + (size_t)ar1 * K + kt + 16 + ac0);
            bv0 = *(const float4*)(Bp + (size_t)(kt + 16 + br0) * N + bc0);
            bv1 = *(const float4*)(Bp + (size_t)(kt + 16 + br1) * N + bc0);
        }
        #pragma unroll
        for (int kk = 0; kk < 16; kk += 8) {
            wmma::fragment<wmma::matrix_a, 16, 16, 8, wmma::precision::tf32,
                           wmma::row_major> af[2];
            wmma::fragment<wmma::matrix_b, 16, 16, 8, wmma::precision::tf32,
                           wmma::row_major> bf[4];
            #pragma unroll
            for (int i = 0; i < 2; i++) {
                wmma::load_matrix_sync(af[i],
                    &As[(wr * 32 + i * 16) * AS_STRIDE + kk], AS_STRIDE);
                #pragma unroll
                for (int t = 0; t < af[i].num_elements; t++)
                    af[i].x[t] = wmma::__float_to_tf32(af[i].x[t]);
            }
            #pragma unroll
            for (int j = 0; j < 4; j++) {
                wmma::load_matrix_sync(bf[j],
                    &Bs[kk * BS_STRIDE + wc * 64 + j * 16], BS_STRIDE);
                #pragma unroll
                for (int t = 0; t < bf[j].num_elements; t++)
                    bf[j].x[t] = wmma::__float_to_tf32(bf[j].x[t]);
            }
            #pragma unroll
            for (int i = 0; i < 2; i++)
                #pragma unroll
                for (int j = 0; j < 4; j++)
                    wmma::mma_sync(acc[i][j], af[i], bf[j], acc[i][j]);
        }
        __syncthreads();
    }

    #pragma unroll
    for (int i = 0; i < 2; i++)
        #pragma unroll
        for (int j = 0; j < 4; j++)
            wmma::store_matrix_sync(
                C + (size_t)(brow + wr * 32 + i * 16) * N + bcol + wc * 64 + j * 16,
                acc[i][j], N, wmma::mem_row_major);
}

__global__ __launch_bounds__(256, 2) void tf32_gemm_kernel(
    const float* __restrict__ A, const float* __restrict__ B, float* __restrict__ C,
    int M, int N, int K)
{
    __shared__ float As[128 * AS_STRIDE];
    __shared__ float Bs[16 * BS_STRIDE];
    tf32_tile_body(A, B, C, N, K, blockIdx.y * 128, blockIdx.x * 128, As, Bs);
}

// Fused QKV projection: one launch covers all three output matrices.
// blockIdx.x: [0,32) -> Q cols, [32,40) -> K cols, [40,48) -> V cols.
__global__ __launch_bounds__(256, 2) void qkv_gemm_kernel(
    const float* __restrict__ x,
    const float* __restrict__ wq, const float* __restrict__ wk,
    const float* __restrict__ wv,
    float* __restrict__ q, float* __restrict__ k, float* __restrict__ v,
    int K)
{
    __shared__ float As[128 * AS_STRIDE];
    __shared__ float Bs[16 * BS_STRIDE];
    const int bx = blockIdx.x;
    const float* W;
    float* C;
    int N, bcol;
    if (bx < 32)      { W = wq; C = q; N = NH  * HD; bcol = bx * 128; }
    else if (bx < 40) { W = wk; C = k; N = NKV * HD; bcol = (bx - 32) * 128; }
    else              { W = wv; C = v; N = NKV * HD; bcol = (bx - 40) * 128; }
    tf32_tile_body(x, W, C, N, K, blockIdx.y * 128, bcol, As, Bs);
}

// ---------------- RoPE (in-place on q or k) -----------------------------------
__global__ void rope_kernel(float* __restrict__ t, const float* __restrict__ cs,
                            const float* __restrict__ sn, int nheads, int S, int npairs)
{
    int idx = blockIdx.x * blockDim.x + threadIdx.x;
    if (idx >= npairs) return;
    int d   = idx & 63;
    int h   = (idx >> 6) % nheads;
    int tok = idx / (64 * nheads);
    int s   = tok % S;          // start_pos = 0
    float c  = cs[s * 64 + d];
    float si = sn[s * 64 + d];
    float* base = t + ((size_t)tok * nheads + h) * HD;
    float x1 = base[d], x2 = base[d + 64];
    base[d]      = x1 * c - x2 * si;
    base[d + 64] = x1 * si + x2 * c;
}

// ---------------- Flash attention: Bq=Bk=128, causal, GQA ---------------------
#define QT_STRIDE 132
#define SM_QT  0
#define SM_KT  (128 * 132)                 // reused as P^T after S is computed
#define SM_V   (SM_KT + 128 * 132)
#define SM_RED (SM_V + 128 * 128)
#define SM_FLOATS (SM_RED + 128 * 17)      // 52352 floats = 209408 bytes

__global__ __launch_bounds__(256, 1) void attn_kernel(int S)
{
    extern __shared__ float smx[];
    float* Qt  = smx + SM_QT;    // [d][r]  (Q^T, pre-scaled)
    float* Kt  = smx + SM_KT;    // [d][c]  (K^T), later P^T [c][r]
    float* Vs  = smx + SM_V;     // [j][c]
    float* red = smx + SM_RED;   // [row][16] reduction buffer, stride 17

    const int tid = threadIdx.x;
    const int tx = tid & 15, ty = tid >> 4;
    const int qb = blockIdx.x;
    const int h  = blockIdx.y;
    const int b  = blockIdx.z;
    const int kvh = h >> 2;              // 32 heads / 8 kv heads = groups of 4
    const int qbase = qb * 128;
    const float scale = 0.08838834764831845f;  // 1/sqrt(128)

    // load Q^T (scaled)
    {
        const float* qsrc = g_q + ((size_t)(b * S + qbase)) * (NH * HD) + h * HD;
        #pragma unroll
        for (int it = 0; it < 16; it++) {
            int f4 = tid + it * 256;
            int r  = f4 >> 5;
            int dc = (f4 & 31) * 4;
            float4 v = *(const float4*)(qsrc + (size_t)r * (NH * HD) + dc);
            Qt[(dc + 0) * QT_STRIDE + r] = v.x * scale;
            Qt[(dc + 1) * QT_STRIDE + r] = v.y * scale;
            Qt[(dc + 2) * QT_STRIDE + r] = v.z * scale;
            Qt[(dc + 3) * QT_STRIDE + r] = v.w * scale;
        }
    }

    unsigned long long o2[8][4];
    float m[8], l[8];
    #pragma unroll
    for (int i = 0; i < 8; i++) {
        m[i] = -1e30f; l[i] = 0.f;
        #pragma unroll
        for (int t = 0; t < 4; t++) o2[i][t] = 0ull;
    }

    for (int jb = 0; jb <= qb; jb++) {
        __syncthreads();   // previous-tile smem reads done (and Qt stores, 1st iter)
        {
            const float* ksrc = g_k + ((size_t)(b * S + jb * 128)) * (NKV * HD) + kvh * HD;
            const float* vsrc = g_v + ((size_t)(b * S + jb * 128)) * (NKV * HD) + kvh * HD;
            #pragma unroll
            for (int it = 0; it < 16; it++) {
                int f4 = tid + it * 256;
                int r  = f4 >> 5;
                int dc = (f4 & 31) * 4;
                float4 k4 = *(const float4*)(ksrc + (size_t)r * (NKV * HD) + dc);
                Kt[(dc + 0) * QT_STRIDE + r] = k4.x;
                Kt[(dc + 1) * QT_STRIDE + r] = k4.y;
                Kt[(dc + 2) * QT_STRIDE + r] = k4.z;
                Kt[(dc + 3) * QT_STRIDE + r] = k4.w;
                float4 v4 = *(const float4*)(vsrc + (size_t)r * (NKV * HD) + dc);
                *(float4*)&Vs[r * 128 + dc] = v4;
            }
        }
        __syncthreads();

        // S = (Q*scale) @ K^T  — rows ty*8+i, cols tx*8+j
        unsigned long long s2[8][4];
        #pragma unroll
        for (int i = 0; i < 8; i++)
            #pragma unroll
            for (int t = 0; t < 4; t++) s2[i][t] = 0ull;

        #pragma unroll 2
        for (int d = 0; d < 128; d++) {
            float a[8];
            F8 bu;
            *(float4*)&a[0] = *(const float4*)&Qt[d * QT_STRIDE + ty * 8];
            *(float4*)&a[4] = *(const float4*)&Qt[d * QT_STRIDE + ty * 8 + 4];
            bu.v[0] = *(const float4*)&Kt[d * QT_STRIDE + tx * 8];
            bu.v[1] = *(const float4*)&Kt[d * QT_STRIDE + tx * 8 + 4];
            #pragma unroll
            for (int i = 0; i < 8; i++) {
                unsigned long long aa = pk2(a[i], a[i]);
                #pragma unroll
                for (int t = 0; t < 4; t++)
                    ffma2(s2[i][t], aa, bu.u[t]);
            }
        }

        float s[8][8];
        #pragma unroll
        for (int i = 0; i < 8; i++)
            #pragma unroll
            for (int t = 0; t < 4; t++) upk2(s2[i][t], s[i][2 * t], s[i][2 * t + 1]);

        if (jb == qb) {   // causal mask on diagonal tile (qbase == kbase)
            #pragma unroll
            for (int i = 0; i < 8; i++)
                #pragma unroll
                for (int j = 0; j < 8; j++)
                    if (tx * 8 + j > ty * 8 + i) s[i][j] = -1e30f;
        }

        // row-max partials
        #pragma unroll
        for (int i = 0; i < 8; i++) {
            float mx = s[i][0];
            #pragma unroll
            for (int j = 1; j < 8; j++) mx = fmaxf(mx, s[i][j]);
            red[(ty * 8 + i) * 17 + tx] = mx;
        }
        __syncthreads();

        float mnew[8], alpha[8];
        #pragma unroll
        for (int i = 0; i < 8; i++) {
            float mt = m[i];
            #pragma unroll
            for (int t = 0; t < 16; t++) mt = fmaxf(mt, red[(ty * 8 + i) * 17 + t]);
            mnew[i]  = mt;
            alpha[i] = __expf(m[i] - mt);
            m[i]     = mt;
        }
        __syncthreads();  // max reads done before red is reused for sums

        // p = exp(s - m), row-sum partials, rescale O, write P^T over Kt
        #pragma unroll
        for (int i = 0; i < 8; i++) {
            float rs = 0.f;
            #pragma unroll
            for (int j = 0; j < 8; j++) {
                float p = __expf(s[i][j] - mnew[i]);
                s[i][j] = p;
                rs += p;
            }
            red[(ty * 8 + i) * 17 + tx] = rs;
            unsigned long long a2 = pk2(alpha[i], alpha[i]);
            #pragma unroll
            for (int t = 0; t < 4; t++) o2[i][t] = mul2(o2[i][t], a2);
        }
        #pragma unroll
        for (int j = 0; j < 8; j++) {   // P^T[key][qrow]
            float4 p0 = make_float4(s[0][j], s[1][j], s[2][j], s[3][j]);
            float4 p1 = make_float4(s[4][j], s[5][j], s[6][j], s[7][j]);
            *(float4*)&Kt[(tx * 8 + j) * QT_STRIDE + ty * 8]     = p0;
            *(float4*)&Kt[(tx * 8 + j) * QT_STRIDE + ty * 8 + 4] = p1;
        }
        __syncthreads();

        #pragma unroll
        for (int i = 0; i < 8; i++) {
            float rs = 0.f;
            #pragma unroll
            for (int t = 0; t < 16; t++) rs += red[(ty * 8 + i) * 17 + t];
            l[i] = l[i] * alpha[i] + rs;
        }

        // O += P @ V
        #pragma unroll 2
        for (int j = 0; j < 128; j++) {
            float pf[8];
            F8 vv;
            *(float4*)&pf[0] = *(const float4*)&Kt[j * QT_STRIDE + ty * 8];
            *(float4*)&pf[4] = *(const float4*)&Kt[j * QT_STRIDE + ty * 8 + 4];
            vv.v[0] = *(const float4*)&Vs[j * 128 + tx * 8];
            vv.v[1] = *(const float4*)&Vs[j * 128 + tx * 8 + 4];
            #pragma unroll
            for (int i = 0; i < 8; i++) {
                unsigned long long pp = pk2(pf[i], pf[i]);
                #pragma unroll
                for (int t = 0; t < 4; t++)
                    ffma2(o2[i][t], pp, vv.u[t]);
            }
        }
    }

    // epilogue: O /= l, write [tok][h*128+d]
    float* odst = g_att + ((size_t)(b * S + qbase + ty * 8)) * (NH * HD) + h * HD + tx * 8;
    #pragma unroll
    for (int i = 0; i < 8; i++) {
        float inv = 1.0f / l[i];
        float ov[8];
        #pragma unroll
        for (int t = 0; t < 4; t++) upk2(o2[i][t], ov[2 * t], ov[2 * t + 1]);
        #pragma unroll
        for (int t = 0; t < 8; t++) ov[t] *= inv;
        *(float4*)(odst + (size_t)i * (NH * HD))     = *(float4*)&ov[0];
        *(float4*)(odst + (size_t)i * (NH * HD) + 4) = *(float4*)&ov[4];
    }
}

// ---------------- launch -------------------------------------------------------
extern "C" void kernel_launch(void* const* d_in, const int* in_sizes, int n_in,
                              void* d_out, int out_size)
{
    const float* x  = (const float*)d_in[0];
    const float* wq = (const float*)d_in[1];
    const float* wk = (const float*)d_in[2];
    const float* wv = (const float*)d_in[3];
    const float* wo = (const float*)d_in[4];
    const float* fc = (const float*)d_in[5];
    const float* fs = (const float*)d_in[6];
    float* out = (float*)d_out;

    const int S = in_sizes[5] / (HD / 2);        // freqs_cos: [S, 64]
    const int H = in_sizes[1] / (NH * HD);       // 4096
    const int B = in_sizes[0] / (S * H);         // 2
    const int M = B * S;                         // 2048

    float *q, *k, *v, *att;
    cudaGetSymbolAddress((void**)&q,   g_q);
    cudaGetSymbolAddress((void**)&k,   g_k);
    cudaGetSymbolAddress((void**)&v,   g_v);
    cudaGetSymbolAddress((void**)&att, g_att);

    cudaFuncSetAttribute(attn_kernel, cudaFuncAttributeMaxDynamicSharedMemorySize,
                         SM_FLOATS * 4);

    dim3 thr(256);
    // Fused QKV projection: 48 column-tiles (32 Q + 8 K + 8 V) x 16 row-tiles.
    qkv_gemm_kernel<<<dim3(48, M / 128), thr>>>(x, wq, wk, wv, q, k, v, H);

    const int npq = M * NH  * (HD / 2);
    const int npk = M * NKV * (HD / 2);
    rope_kernel<<<(npq + 255) / 256, 256>>>(q, fc, fs, NH,  S, npq);
    rope_kernel<<<(npk + 255) / 256, 256>>>(k, fc, fs, NKV, S, npk);

    attn_kernel<<<dim3(S / 128, NH, B), thr, SM_FLOATS * 4>>>(S);

    tf32_gemm_kernel<<<dim3(H / 128, M / 128), thr>>>(att, wo, out, M, H, NH * HD);
}